// round 15
// baseline (speedup 1.0000x reference)
#include <cuda_runtime.h>
#include <cuda_bf16.h>
#include <math.h>
#include <stdint.h>

// ---------------------------------------------------------------------------
// HybridTTLayer via mma.sync bf16 tensor cores (plain sm_100 target).
// fp32 emulated as bf16 hi+lo split, 3-product MMA.
// R15 = R14 (best: 2484us) + LN folded into the dense GEMMs per-kernel:
//   LN(t)@W = iv*(t@(gamma.*W)) - mu*iv*(gamma^T W) + beta^T W
// so post-dense and post-gate share A = t-split (ln2 buffers eliminated,
// LN2 -> stats only), pre-dense and pre-gate share A = x-split.
// GEMM mainloop/tiling identical to R14: CTA 128x128, 4 warps, 64x64 warp
// tile, BK=32, 3-stage cp.async, 2 CTAs/SM.
// ---------------------------------------------------------------------------

#define NTOK   4096
#define DIN    1024
#define DOUT   4096

#define OP_NONE   0
#define OP_GELU   1
#define OP_GATE   2
#define OP_LNGELU 3

// GEMM tiling
#define BM 128
#define BN 128
#define BK 32
#define NTHR 128
#define STAGES 3
#define OFF_AH 0
#define OFF_AL 8192
#define OFF_BH 16384
#define OFF_BL 24576
#define STAGE_BYTES 32768
#define GEMM_SMEM (STAGES * STAGE_BYTES)   // 98304 -> 2 CTAs/SM

// swizzled byte offset of 16B chunk c (0..3) in row r (64B rows)
__device__ __forceinline__ uint32_t swz(int r, int c) {
    return (uint32_t)(r * 64 + ((c ^ ((r >> 1) & 3)) << 4));
}

// ------------------------- scratch (static device memory) ------------------
__device__ float g_h1 [NTOK * DIN];
__device__ float g_t  [NTOK * DOUT];
__device__ float g_h2 [NTOK * DOUT];
__device__ float g_gb [NTOK * DOUT];      // post gate sigmoid buffer
__device__ float g_a01[8 * 8 * 8 * 16 * 16];
__device__ float g_mu1[NTOK], g_iv1[NTOK];
__device__ float g_mu2[NTOK], g_iv2[NTOK];
__device__ float g_vGW1[DIN],  g_vBW1[DIN];
__device__ float g_vGW2[DOUT], g_vBW2[DOUT];
__device__ __nv_bfloat16 g_xH   [NTOK * DIN],  g_xL   [NTOK * DIN];
__device__ __nv_bfloat16 g_hpreH[NTOK * DIN],  g_hpreL[NTOK * DIN];
__device__ __nv_bfloat16 g_tH   [NTOK * DOUT], g_tL   [NTOK * DOUT];
__device__ __nv_bfloat16 g_preDwTH [DIN * DIN],   g_preDwTL [DIN * DIN];   // (gamma.*W)^T
__device__ __nv_bfloat16 g_preGwTH [DIN * DIN],   g_preGwTL [DIN * DIN];
__device__ __nv_bfloat16 g_wttTH   [DOUT * DIN],  g_wttTL   [DOUT * DIN];
__device__ __nv_bfloat16 g_postDwTH[DOUT * DOUT], g_postDwTL[DOUT * DOUT]; // (gamma.*W)^T
__device__ __nv_bfloat16 g_postGwTH[DOUT * DOUT], g_postGwTL[DOUT * DOUT];

// ------------------------- helpers -----------------------------------------
__device__ __forceinline__ uint32_t smem_u32(const void* p) {
    uint32_t a;
    asm("{ .reg .u64 t; cvta.to.shared.u64 t, %1; cvt.u32.u64 %0, t; }"
        : "=r"(a) : "l"(p));
    return a;
}
__device__ __forceinline__ void cp16(uint32_t s, const void* g) {
    asm volatile("cp.async.cg.shared.global [%0], [%1], 16;" :: "r"(s), "l"(g));
}
#define CP_COMMIT() asm volatile("cp.async.commit_group;")
#define CP_WAIT1()  asm volatile("cp.async.wait_group 1;")
#define CP_WAIT0()  asm volatile("cp.async.wait_group 0;")

__device__ __forceinline__ void ldmx4(uint32_t* r, uint32_t a) {
    asm volatile("ldmatrix.sync.aligned.m8n8.x4.shared.b16 {%0,%1,%2,%3}, [%4];"
        : "=r"(r[0]), "=r"(r[1]), "=r"(r[2]), "=r"(r[3]) : "r"(a));
}
__device__ __forceinline__ void mma_bf16(float* d, const uint32_t* a, const uint32_t* b) {
    asm volatile("mma.sync.aligned.m16n8k16.row.col.f32.bf16.bf16.f32 "
        "{%0,%1,%2,%3}, {%4,%5,%6,%7}, {%8,%9}, {%0,%1,%2,%3};"
        : "+f"(d[0]), "+f"(d[1]), "+f"(d[2]), "+f"(d[3])
        : "r"(a[0]), "r"(a[1]), "r"(a[2]), "r"(a[3]), "r"(b[0]), "r"(b[1]));
}
__device__ __forceinline__ float gelu_exact(float v) {
    return 0.5f * v * (1.0f + erff(v * 0.70710678118654752f));
}
__device__ __forceinline__ float sigmoidf_(float v) {
    return 1.0f / (1.0f + __expf(-v));
}
__device__ __forceinline__ void split_bf16(float v, __nv_bfloat16& h, __nv_bfloat16& l) {
    h = __float2bfloat16_rn(v);
    l = __float2bfloat16_rn(v - __bfloat162float(h));
}

// ------------------------- row stats (mean, inv-std) [+ optional split] -----
template <int EPT, bool SPLIT>
__global__ __launch_bounds__(256) void stats_split_kernel(
    const float* __restrict__ in, float* __restrict__ muO, float* __restrict__ ivO,
    __nv_bfloat16* __restrict__ oH, __nv_bfloat16* __restrict__ oL, int D)
{
    const int row = blockIdx.x;
    const int tid = threadIdx.x;
    const float* rp = in + (size_t)row * D;

    float v[EPT];
    float s = 0.f;
#pragma unroll
    for (int e = 0; e < EPT; e++) { v[e] = rp[tid + e * 256]; s += v[e]; }

    __shared__ float red[8];
    __shared__ float sMean, sVar;
#pragma unroll
    for (int o = 16; o > 0; o >>= 1) s += __shfl_down_sync(0xffffffffu, s, o);
    if ((tid & 31) == 0) red[tid >> 5] = s;
    __syncthreads();
    if (tid < 8) {
        float w = red[tid];
#pragma unroll
        for (int o = 4; o > 0; o >>= 1) w += __shfl_down_sync(0xffu, w, o);
        if (tid == 0) sMean = w / (float)D;
    }
    __syncthreads();
    const float mean = sMean;

    float q = 0.f;
#pragma unroll
    for (int e = 0; e < EPT; e++) { float d = v[e] - mean; q += d * d; }
#pragma unroll
    for (int o = 16; o > 0; o >>= 1) q += __shfl_down_sync(0xffffffffu, q, o);
    if ((tid & 31) == 0) red[tid >> 5] = q;
    __syncthreads();
    if (tid < 8) {
        float w = red[tid];
#pragma unroll
        for (int o = 4; o > 0; o >>= 1) w += __shfl_down_sync(0xffu, w, o);
        if (tid == 0) sVar = w / (float)D;
    }
    __syncthreads();
    if (tid == 0) { muO[row] = mean; ivO[row] = rsqrtf(sVar + 1e-6f); }

    if (SPLIT) {
        const size_t rb = (size_t)row * D;
#pragma unroll
        for (int e = 0; e < EPT; e++) {
            int c = tid + e * 256;
            __nv_bfloat16 h, l;
            split_bf16(v[e], h, l);
            oH[rb + c] = h; oL[rb + c] = l;
        }
    }
}

// ------------------------- TT operator materialization ----------------------
__global__ __launch_bounds__(256) void build_a01_kernel(
    const float* __restrict__ c0, const float* __restrict__ c1,
    float* __restrict__ a01)
{
    int idx = blockIdx.x * 256 + threadIdx.x;   // 131072
    int s = idx & 15, y = (idx >> 4) & 15, b = (idx >> 8) & 7;
    int x = (idx >> 11) & 7, a = idx >> 14;
    float acc = 0.f;
#pragma unroll
    for (int r = 0; r < 16; r++)
        acc += c0[a * 128 + x * 16 + r] * c1[((r * 8 + b) * 16 + y) * 16 + s];
    a01[idx] = acc;
}

__global__ __launch_bounds__(256) void build_wttT_kernel(
    const float* __restrict__ a01, const float* __restrict__ c2,
    __nv_bfloat16* __restrict__ wH, __nv_bfloat16* __restrict__ wL)
{
    int idx = blockIdx.x * 256 + threadIdx.x;   // 4096*1024
    int in  = idx & 1023;
    int out = idx >> 10;
    int z = out & 31, y = (out >> 5) & 15, x = out >> 9;
    int c = in & 15,  b = (in >> 4) & 7,   a = in >> 7;
    const float* ap = a01 + (((a * 8 + x) * 8 + b) * 16 + y) * 16;
    float acc = 0.f;
#pragma unroll
    for (int s = 0; s < 16; s++)
        acc += ap[s] * c2[(s * 16 + c) * 32 + z];
    __nv_bfloat16 h, l;
    split_bf16(acc, h, l);
    wH[idx] = h; wL[idx] = l;
}

// ------------------------- batched weight transpose + split ------------------
// z=0: dense weight scaled by gamma[k]; z=1: gate weight unscaled.
__global__ __launch_bounds__(256) void transpose_split2_kernel(
    const float* __restrict__ in0, const float* __restrict__ gamma,
    __nv_bfloat16* __restrict__ o0H, __nv_bfloat16* __restrict__ o0L,
    const float* __restrict__ in1, __nv_bfloat16* __restrict__ o1H,
    __nv_bfloat16* __restrict__ o1L, int K, int N)
{
    const bool zz = (blockIdx.z != 0);
    const float* in = zz ? in1 : in0;
    __nv_bfloat16* oH = zz ? o1H : o0H;
    __nv_bfloat16* oL = zz ? o1L : o0L;
    __shared__ float tile[32][33];
    int n0 = blockIdx.x * 32, k0 = blockIdx.y * 32;
    int tx = threadIdx.x & 31, ty = threadIdx.x >> 5;
#pragma unroll
    for (int i = 0; i < 4; i++)
        tile[ty + i * 8][tx] = in[(size_t)(k0 + ty + i * 8) * N + n0 + tx];
    __syncthreads();
    const float gk = zz ? 1.f : gamma[k0 + tx];
#pragma unroll
    for (int i = 0; i < 4; i++) {
        float v = tile[tx][ty + i * 8] * gk;
        __nv_bfloat16 h, l;
        split_bf16(v, h, l);
        size_t o = (size_t)(n0 + ty + i * 8) * K + k0 + tx;
        oH[o] = h; oL[o] = l;
    }
}

// ------------------------- column sums: gamma^T W, beta^T W ------------------
__global__ __launch_bounds__(128) void colsum_kernel(
    const float* __restrict__ W, const float* __restrict__ gamma,
    const float* __restrict__ beta, float* __restrict__ vGW,
    float* __restrict__ vBW, int K, int N)
{
    int n = blockIdx.x * 128 + threadIdx.x;
    float sg = 0.f, sb = 0.f;
#pragma unroll 4
    for (int k = 0; k < K; k++) {
        float w = W[(size_t)k * N + n];
        sg += gamma[k] * w;
        sb += beta[k] * w;
    }
    vGW[n] = sg; vBW[n] = sb;
}

// ------------------------- streaming combine: out = g*h + (1-g)*r -----------
__global__ __launch_bounds__(256) void combine_kernel(
    const float* __restrict__ g, const float* __restrict__ h,
    const float* __restrict__ r, float* __restrict__ out, int n4)
{
    int i = blockIdx.x * 256 + threadIdx.x;
    if (i < n4) {
        float4 gv = ((const float4*)g)[i];
        float4 hv = ((const float4*)h)[i];
        float4 rv = ((const float4*)r)[i];
        float4 o;
        o.x = gv.x * hv.x + (1.f - gv.x) * rv.x;
        o.y = gv.y * hv.y + (1.f - gv.y) * rv.y;
        o.z = gv.z * hv.z + (1.f - gv.z) * rv.z;
        o.w = gv.w * hv.w + (1.f - gv.w) * rv.w;
        ((float4*)out)[i] = o;
    }
}

// ------------------------- core mainloop (shared) ----------------------------
__device__ __forceinline__ void load_stage4(
    uint32_t sbase,
    const __nv_bfloat16* __restrict__ Ah, const __nv_bfloat16* __restrict__ Al,
    const __nv_bfloat16* __restrict__ Bh, const __nv_bfloat16* __restrict__ Bl,
    int aRow0, int bRow0, int K, int k0, int tid)
{
#pragma unroll
    for (int i = 0; i < 4; i++) {
        int idx = tid + i * NTHR;
        int r = idx >> 2, c = idx & 3;
        uint32_t so = swz(r, c);
        size_t ga = (size_t)(aRow0 + r) * K + k0 + c * 8;
        size_t gb = (size_t)(bRow0 + r) * K + k0 + c * 8;
        cp16(sbase + OFF_AH + so, Ah + ga);
        cp16(sbase + OFF_AL + so, Al + ga);
        cp16(sbase + OFF_BH + so, Bh + gb);
        cp16(sbase + OFF_BL + so, Bl + gb);
    }
}

// mainloop producing acc[4][8][4] for one 128x128 tile; warp tile 64x64.
__device__ __forceinline__ void gemm_mainloop(
    uint32_t sm, float acc[4][8][4],
    const __nv_bfloat16* __restrict__ Ah, const __nv_bfloat16* __restrict__ Al,
    const __nv_bfloat16* __restrict__ Bh, const __nv_bfloat16* __restrict__ Bl,
    int blockM, int blockN, int K, int tid, int lane, int wm, int wn)
{
    const int nk = K / BK;
#pragma unroll
    for (int s = 0; s < STAGES - 1; s++) {
        load_stage4(sm + s * STAGE_BYTES, Ah, Al, Bh, Bl, blockM, blockN, K, s * BK, tid);
        CP_COMMIT();
    }
    const int aRow = lane & 15;
    const int aHi  = lane >> 4;
    const int bRow = wn + (lane & 7) + ((lane >> 4) << 3);
    const int bHi  = (lane >> 3) & 1;
    const int sA = ((aRow >> 1) & 3);
    const int sB = ((bRow >> 1) & 3);   // invariant under +16 row steps

    for (int t = 0; t < nk; t++) {
        CP_WAIT1();
        __syncthreads();
        const int pf = t + STAGES - 1;
        const uint32_t sb = sm + (t % STAGES) * STAGE_BYTES;

#pragma unroll
        for (int ks = 0; ks < 2; ks++) {
            const uint32_t aChunk = (uint32_t)(((ks * 2 + aHi) ^ sA) << 4);
            const uint32_t bChunk = (uint32_t)(((ks * 2 + bHi) ^ sB) << 4);
            uint32_t ah[4][4], al[4][4];
#pragma unroll
            for (int mt = 0; mt < 4; mt++) {
                const uint32_t ra = (uint32_t)((wm + mt * 16 + aRow) * 64) + aChunk;
                ldmx4(ah[mt], sb + OFF_AH + ra);
                ldmx4(al[mt], sb + OFF_AL + ra);
            }
            if (ks == 0) {
                if (pf < nk)
                    load_stage4(sm + (pf % STAGES) * STAGE_BYTES, Ah, Al, Bh, Bl,
                                blockM, blockN, K, pf * BK, tid);
                CP_COMMIT();
            }
            uint32_t bh[2][4], bl[2][4];
            {
                const uint32_t rg = (uint32_t)(bRow * 64) + bChunk;
                ldmx4(bh[0], sb + OFF_BH + rg);
                ldmx4(bl[0], sb + OFF_BL + rg);
            }
#pragma unroll
            for (int g = 0; g < 4; g++) {
                const int cur = g & 1;
                const int nxt = cur ^ 1;
                if (g < 3) {
                    const uint32_t rg = (uint32_t)((bRow + (g + 1) * 16) * 64) + bChunk;
                    ldmx4(bh[nxt], sb + OFF_BH + rg);
                    ldmx4(bl[nxt], sb + OFF_BL + rg);
                }
#pragma unroll
                for (int mt = 0; mt < 4; mt++) mma_bf16(acc[mt][2 * g + 0], ah[mt], bh[cur] + 0);
#pragma unroll
                for (int mt = 0; mt < 4; mt++) mma_bf16(acc[mt][2 * g + 1], ah[mt], bh[cur] + 2);
#pragma unroll
                for (int mt = 0; mt < 4; mt++) mma_bf16(acc[mt][2 * g + 0], ah[mt], bl[cur] + 0);
#pragma unroll
                for (int mt = 0; mt < 4; mt++) mma_bf16(acc[mt][2 * g + 1], ah[mt], bl[cur] + 2);
#pragma unroll
                for (int mt = 0; mt < 4; mt++) mma_bf16(acc[mt][2 * g + 0], al[mt], bh[cur] + 0);
#pragma unroll
                for (int mt = 0; mt < 4; mt++) mma_bf16(acc[mt][2 * g + 1], al[mt], bh[cur] + 2);
            }
        }
    }
    CP_WAIT0();
}

// ------------------------- GEMM kernels --------------------------------------
// OP_LNGELU: v = iv[m]*acc - mu[m]*iv[m]*vGW[n] + vBW[n] + bias[n]; gelu(v)
template <int OP, bool WF32, bool WSPLIT>
__global__ __launch_bounds__(NTHR, 2) void mma_gemm_kernel(
    const __nv_bfloat16* __restrict__ Ah, const __nv_bfloat16* __restrict__ Al,
    const __nv_bfloat16* __restrict__ Bh, const __nv_bfloat16* __restrict__ Bl,
    const float* __restrict__ bias, const float* __restrict__ Hm,
    const float* __restrict__ Rm,
    const float* __restrict__ mu, const float* __restrict__ iv,
    const float* __restrict__ vGW, const float* __restrict__ vBW,
    float* __restrict__ CF, __nv_bfloat16* __restrict__ CH,
    __nv_bfloat16* __restrict__ CL, int M, int N, int K)
{
    extern __shared__ char smem[];
    const uint32_t sm = smem_u32(smem);
    const int tid  = threadIdx.x;
    const int lane = tid & 31;
    const int wid  = tid >> 5;
    const int blockM = blockIdx.x * BM;
    const int blockN = blockIdx.y * BN;
    const int wm = (wid >> 1) * 64;
    const int wn = (wid & 1) * 64;

    float acc[4][8][4];
#pragma unroll
    for (int i = 0; i < 4; i++)
#pragma unroll
        for (int j = 0; j < 8; j++)
#pragma unroll
            for (int e = 0; e < 4; e++) acc[i][j][e] = 0.f;

    gemm_mainloop(sm, acc, Ah, Al, Bh, Bl, blockM, blockN, K, tid, lane, wm, wn);

    const int r0 = lane >> 2;
    const int c0 = (lane & 3) * 2;
#pragma unroll
    for (int mt = 0; mt < 4; mt++) {
#pragma unroll
        for (int half = 0; half < 2; half++) {
            const int m = blockM + wm + mt * 16 + r0 + half * 8;
            const size_t base = (size_t)m * N;
            float iv_m = 0.f, miv = 0.f;
            if (OP == OP_LNGELU) { iv_m = iv[m]; miv = mu[m] * iv_m; }
#pragma unroll
            for (int nt = 0; nt < 8; nt++) {
                const int n = blockN + wn + nt * 8 + c0;
                float v0 = acc[mt][nt][half * 2 + 0];
                float v1 = acc[mt][nt][half * 2 + 1];
                if (OP == OP_GELU) {
                    v0 = gelu_exact(v0 + bias[n]);
                    v1 = gelu_exact(v1 + bias[n + 1]);
                } else if (OP == OP_LNGELU) {
                    v0 = gelu_exact(iv_m * v0 - miv * vGW[n]     + vBW[n]     + bias[n]);
                    v1 = gelu_exact(iv_m * v1 - miv * vGW[n + 1] + vBW[n + 1] + bias[n + 1]);
                } else if (OP == OP_GATE) {
                    float2 hh = *(const float2*)(Hm + base + n);
                    float2 rr = *(const float2*)(Rm + base + n);
                    float g0 = sigmoidf_(v0 + bias[n]);
                    float g1 = sigmoidf_(v1 + bias[n + 1]);
                    v0 = g0 * hh.x + (1.f - g0) * rr.x;
                    v1 = g1 * hh.y + (1.f - g1) * rr.y;
                }
                if (WF32) *(float2*)(CF + base + n) = make_float2(v0, v1);
                if (WSPLIT) {
                    __nv_bfloat16 hA, lA, hB, lB;
                    split_bf16(v0, hA, lA);
                    split_bf16(v1, hB, lB);
                    __nv_bfloat162 ph; ph.x = hA; ph.y = hB;
                    __nv_bfloat162 pl; pl.x = lA; pl.y = lB;
                    *(__nv_bfloat162*)(CH + base + n) = ph;
                    *(__nv_bfloat162*)(CL + base + n) = pl;
                }
            }
        }
    }
}

// merged post GEMM, shared A = t-split:
//   z=0: B=(gamma.*Wd)^T -> h2 = gelu(LN-corrected acc + db)
//   z=1: B=Wg^T          -> g  = sigmoid(acc + gb)
__global__ __launch_bounds__(NTHR, 2) void post_merged_kernel(
    const __nv_bfloat16* __restrict__ AH, const __nv_bfloat16* __restrict__ AL,
    const __nv_bfloat16* __restrict__ BdH, const __nv_bfloat16* __restrict__ BdL,
    const __nv_bfloat16* __restrict__ BgH, const __nv_bfloat16* __restrict__ BgL,
    const float* __restrict__ mu, const float* __restrict__ iv,
    const float* __restrict__ vGW, const float* __restrict__ vBW,
    const float* __restrict__ db, const float* __restrict__ gbv,
    float* __restrict__ h2, float* __restrict__ gbuf, int M, int N, int K)
{
    extern __shared__ char smem[];
    const uint32_t sm = smem_u32(smem);
    const int tid  = threadIdx.x;
    const int lane = tid & 31;
    const int wid  = tid >> 5;
    const int blockM = blockIdx.x * BM;
    const int blockN = blockIdx.y * BN;
    const int z = blockIdx.z;
    const int wm = (wid >> 1) * 64;
    const int wn = (wid & 1) * 64;

    const __nv_bfloat16* Bh = z ? BgH : BdH;
    const __nv_bfloat16* Bl = z ? BgL : BdL;
    const float* bias = z ? gbv : db;
    float* CF = z ? gbuf : h2;

    float acc[4][8][4];
#pragma unroll
    for (int i = 0; i < 4; i++)
#pragma unroll
        for (int j = 0; j < 8; j++)
#pragma unroll
            for (int e = 0; e < 4; e++) acc[i][j][e] = 0.f;

    gemm_mainloop(sm, acc, AH, AL, Bh, Bl, blockM, blockN, K, tid, lane, wm, wn);

    const int r0 = lane >> 2;
    const int c0 = (lane & 3) * 2;
#pragma unroll
    for (int mt = 0; mt < 4; mt++) {
#pragma unroll
        for (int half = 0; half < 2; half++) {
            const int m = blockM + wm + mt * 16 + r0 + half * 8;
            const size_t base = (size_t)m * N;
            float iv_m = 0.f, miv = 0.f;
            if (z == 0) { iv_m = iv[m]; miv = mu[m] * iv_m; }
#pragma unroll
            for (int nt = 0; nt < 8; nt++) {
                const int n = blockN + wn + nt * 8 + c0;
                float v0 = acc[mt][nt][half * 2 + 0];
                float v1 = acc[mt][nt][half * 2 + 1];
                if (z == 0) {
                    v0 = gelu_exact(iv_m * v0 - miv * vGW[n]     + vBW[n]     + bias[n]);
                    v1 = gelu_exact(iv_m * v1 - miv * vGW[n + 1] + vBW[n + 1] + bias[n + 1]);
                } else {
                    v0 = sigmoidf_(v0 + bias[n]);
                    v1 = sigmoidf_(v1 + bias[n + 1]);
                }
                *(float2*)(CF + base + n) = make_float2(v0, v1);
            }
        }
    }
}

// ------------------------- launch ------------------------------------------
extern "C" void kernel_launch(void* const* d_in, const int* in_sizes, int n_in,
                              void* d_out, int out_size)
{
    const float* x      = (const float*)d_in[0];
    const float* preG   = (const float*)d_in[1];
    const float* preB   = (const float*)d_in[2];
    const float* preDw  = (const float*)d_in[3];
    const float* preDb  = (const float*)d_in[4];
    const float* preGw  = (const float*)d_in[5];
    const float* preGb  = (const float*)d_in[6];
    const float* core0  = (const float*)d_in[7];
    const float* core1  = (const float*)d_in[8];
    const float* core2  = (const float*)d_in[9];
    const float* postG  = (const float*)d_in[10];
    const float* postB  = (const float*)d_in[11];
    const float* postDw = (const float*)d_in[12];
    const float* postDb = (const float*)d_in[13];
    const float* postGw = (const float*)d_in[14];
    const float* postGb = (const float*)d_in[15];
    float* out = (float*)d_out;

    float *h1, *t, *h2, *gbuf, *a01;
    float *mu1, *iv1, *mu2, *iv2, *vGW1, *vBW1, *vGW2, *vBW2;
    cudaGetSymbolAddress((void**)&h1,   g_h1);
    cudaGetSymbolAddress((void**)&t,    g_t);
    cudaGetSymbolAddress((void**)&h2,   g_h2);
    cudaGetSymbolAddress((void**)&gbuf, g_gb);
    cudaGetSymbolAddress((void**)&a01,  g_a01);
    cudaGetSymbolAddress((void**)&mu1,  g_mu1);
    cudaGetSymbolAddress((void**)&iv1,  g_iv1);
    cudaGetSymbolAddress((void**)&mu2,  g_mu2);
    cudaGetSymbolAddress((void**)&iv2,  g_iv2);
    cudaGetSymbolAddress((void**)&vGW1, g_vGW1);
    cudaGetSymbolAddress((void**)&vBW1, g_vBW1);
    cudaGetSymbolAddress((void**)&vGW2, g_vGW2);
    cudaGetSymbolAddress((void**)&vBW2, g_vBW2);

    __nv_bfloat16 *xH, *xL, *hpreH, *hpreL, *tH, *tL;
    __nv_bfloat16 *preDwTH, *preDwTL, *preGwTH, *preGwTL;
    __nv_bfloat16 *wttTH, *wttTL, *postDwTH, *postDwTL, *postGwTH, *postGwTL;
    cudaGetSymbolAddress((void**)&xH,    g_xH);    cudaGetSymbolAddress((void**)&xL,    g_xL);
    cudaGetSymbolAddress((void**)&hpreH, g_hpreH); cudaGetSymbolAddress((void**)&hpreL, g_hpreL);
    cudaGetSymbolAddress((void**)&tH,    g_tH);    cudaGetSymbolAddress((void**)&tL,    g_tL);
    cudaGetSymbolAddress((void**)&preDwTH,  g_preDwTH);  cudaGetSymbolAddress((void**)&preDwTL,  g_preDwTL);
    cudaGetSymbolAddress((void**)&preGwTH,  g_preGwTH);  cudaGetSymbolAddress((void**)&preGwTL,  g_preGwTL);
    cudaGetSymbolAddress((void**)&wttTH,    g_wttTH);    cudaGetSymbolAddress((void**)&wttTL,    g_wttTL);
    cudaGetSymbolAddress((void**)&postDwTH, g_postDwTH); cudaGetSymbolAddress((void**)&postDwTL, g_postDwTL);
    cudaGetSymbolAddress((void**)&postGwTH, g_postGwTH); cudaGetSymbolAddress((void**)&postGwTL, g_postGwTL);

    cudaFuncSetAttribute(mma_gemm_kernel<OP_LNGELU, true, false>,
                         cudaFuncAttributeMaxDynamicSharedMemorySize, GEMM_SMEM);
    cudaFuncSetAttribute(mma_gemm_kernel<OP_GATE, false, true>,
                         cudaFuncAttributeMaxDynamicSharedMemorySize, GEMM_SMEM);
    cudaFuncSetAttribute(mma_gemm_kernel<OP_NONE, true, true>,
                         cudaFuncAttributeMaxDynamicSharedMemorySize, GEMM_SMEM);
    cudaFuncSetAttribute(post_merged_kernel,
                         cudaFuncAttributeMaxDynamicSharedMemorySize, GEMM_SMEM);

    // --- operator prep (independent of x) ---
    build_a01_kernel<<<131072 / 256, 256>>>(core0, core1, a01);
    build_wttT_kernel<<<(DIN * DOUT) / 256, 256>>>(a01, core2, wttTH, wttTL);
    transpose_split2_kernel<<<dim3(DIN / 32, DIN / 32, 2), 256>>>(
        preDw, preG, preDwTH, preDwTL, preGw, preGwTH, preGwTL, DIN, DIN);
    transpose_split2_kernel<<<dim3(DOUT / 32, DOUT / 32, 2), 256>>>(
        postDw, postG, postDwTH, postDwTL, postGw, postGwTH, postGwTL, DOUT, DOUT);
    colsum_kernel<<<DIN / 128, 128>>>(preDw, preG, preB, vGW1, vBW1, DIN, DIN);
    colsum_kernel<<<DOUT / 128, 128>>>(postDw, postG, postB, vGW2, vBW2, DOUT, DOUT);

    // --- pre block: stats(+x split), LN-folded dense, fused gate ---
    stats_split_kernel<DIN / 256, true><<<NTOK, 256>>>(x, mu1, iv1, xH, xL, DIN);
    mma_gemm_kernel<OP_LNGELU, true, false><<<dim3(NTOK / BM, DIN / BN), NTHR, GEMM_SMEM>>>(
        xH, xL, preDwTH, preDwTL, preDb, nullptr, nullptr,
        mu1, iv1, vGW1, vBW1, h1, nullptr, nullptr, NTOK, DIN, DIN);
    mma_gemm_kernel<OP_GATE, false, true><<<dim3(NTOK / BM, DIN / BN), NTHR, GEMM_SMEM>>>(
        xH, xL, preGwTH, preGwTL, preGb, h1, x,
        nullptr, nullptr, nullptr, nullptr, nullptr, hpreH, hpreL, NTOK, DIN, DIN);

    // --- TT contraction ---
    mma_gemm_kernel<OP_NONE, true, true><<<dim3(NTOK / BM, DOUT / BN), NTHR, GEMM_SMEM>>>(
        hpreH, hpreL, wttTH, wttTL, nullptr, nullptr, nullptr,
        nullptr, nullptr, nullptr, nullptr, t, tH, tL, NTOK, DOUT, DIN);

    // --- post block: stats only, merged dense+gate sharing A=t-split, combine ---
    stats_split_kernel<DOUT / 256, false><<<NTOK, 256>>>(t, mu2, iv2, nullptr, nullptr, DOUT);
    post_merged_kernel<<<dim3(NTOK / BM, DOUT / BN, 2), NTHR, GEMM_SMEM>>>(
        tH, tL, postDwTH, postDwTL, postGwTH, postGwTL,
        mu2, iv2, vGW2, vBW2, postDb, postGb, h2, gbuf, NTOK, DOUT, DOUT);
    combine_kernel<<<(NTOK * DOUT / 4 + 255) / 256, 256>>>(
        gbuf, h2, t, out, NTOK * DOUT / 4);
}

// round 16
// speedup vs baseline: 1.5367x; 1.5367x over previous
#include <cuda_runtime.h>
#include <cuda_bf16.h>
#include <math.h>
#include <stdint.h>

// ---------------------------------------------------------------------------
// HybridTTLayer via mma.sync bf16 tensor cores (plain sm_100 target).
// fp32 emulated as bf16 hi+lo split, 3-product MMA.
// R16 = R15 (LN folded into dense GEMMs: LN(t)@W = iv*(t@(g.*W)) - mu*iv*gW + bW,
// post dense/gate share A=t-split, ln buffers eliminated) with the colsum
// rebuilt as a parallel two-pass deterministic reduction (R15's serial colsum
// cost ~1ms). GEMM: CTA 128x128, 4 warps, 64x64 warp tile, BK=32, 3-stage
// cp.async, 2 CTAs/SM — identical to R14 (2484us best).
// ---------------------------------------------------------------------------

#define NTOK   4096
#define DIN    1024
#define DOUT   4096

#define OP_NONE   0
#define OP_GELU   1
#define OP_GATE   2
#define OP_LNGELU 3

// GEMM tiling
#define BM 128
#define BN 128
#define BK 32
#define NTHR 128
#define STAGES 3
#define OFF_AH 0
#define OFF_AL 8192
#define OFF_BH 16384
#define OFF_BL 24576
#define STAGE_BYTES 32768
#define GEMM_SMEM (STAGES * STAGE_BYTES)   // 98304 -> 2 CTAs/SM

// swizzled byte offset of 16B chunk c (0..3) in row r (64B rows)
__device__ __forceinline__ uint32_t swz(int r, int c) {
    return (uint32_t)(r * 64 + ((c ^ ((r >> 1) & 3)) << 4));
}

// ------------------------- scratch (static device memory) ------------------
__device__ float g_h1 [NTOK * DIN];
__device__ float g_t  [NTOK * DOUT];
__device__ float g_h2 [NTOK * DOUT];
__device__ float g_gb [NTOK * DOUT];      // post gate sigmoid buffer
__device__ float g_a01[8 * 8 * 8 * 16 * 16];
__device__ float g_mu1[NTOK], g_iv1[NTOK];
__device__ float g_mu2[NTOK], g_iv2[NTOK];
__device__ float g_vGW1[DIN],  g_vBW1[DIN];
__device__ float g_vGW2[DOUT], g_vBW2[DOUT];
__device__ float g_pGW[32 * DOUT], g_pBW[32 * DOUT];   // colsum partials
__device__ __nv_bfloat16 g_xH   [NTOK * DIN],  g_xL   [NTOK * DIN];
__device__ __nv_bfloat16 g_hpreH[NTOK * DIN],  g_hpreL[NTOK * DIN];
__device__ __nv_bfloat16 g_tH   [NTOK * DOUT], g_tL   [NTOK * DOUT];
__device__ __nv_bfloat16 g_preDwTH [DIN * DIN],   g_preDwTL [DIN * DIN];   // (gamma.*W)^T
__device__ __nv_bfloat16 g_preGwTH [DIN * DIN],   g_preGwTL [DIN * DIN];
__device__ __nv_bfloat16 g_wttTH   [DOUT * DIN],  g_wttTL   [DOUT * DIN];
__device__ __nv_bfloat16 g_postDwTH[DOUT * DOUT], g_postDwTL[DOUT * DOUT]; // (gamma.*W)^T
__device__ __nv_bfloat16 g_postGwTH[DOUT * DOUT], g_postGwTL[DOUT * DOUT];

// ------------------------- helpers -----------------------------------------
__device__ __forceinline__ uint32_t smem_u32(const void* p) {
    uint32_t a;
    asm("{ .reg .u64 t; cvta.to.shared.u64 t, %1; cvt.u32.u64 %0, t; }"
        : "=r"(a) : "l"(p));
    return a;
}
__device__ __forceinline__ void cp16(uint32_t s, const void* g) {
    asm volatile("cp.async.cg.shared.global [%0], [%1], 16;" :: "r"(s), "l"(g));
}
#define CP_COMMIT() asm volatile("cp.async.commit_group;")
#define CP_WAIT1()  asm volatile("cp.async.wait_group 1;")
#define CP_WAIT0()  asm volatile("cp.async.wait_group 0;")

__device__ __forceinline__ void ldmx4(uint32_t* r, uint32_t a) {
    asm volatile("ldmatrix.sync.aligned.m8n8.x4.shared.b16 {%0,%1,%2,%3}, [%4];"
        : "=r"(r[0]), "=r"(r[1]), "=r"(r[2]), "=r"(r[3]) : "r"(a));
}
__device__ __forceinline__ void mma_bf16(float* d, const uint32_t* a, const uint32_t* b) {
    asm volatile("mma.sync.aligned.m16n8k16.row.col.f32.bf16.bf16.f32 "
        "{%0,%1,%2,%3}, {%4,%5,%6,%7}, {%8,%9}, {%0,%1,%2,%3};"
        : "+f"(d[0]), "+f"(d[1]), "+f"(d[2]), "+f"(d[3])
        : "r"(a[0]), "r"(a[1]), "r"(a[2]), "r"(a[3]), "r"(b[0]), "r"(b[1]));
}
__device__ __forceinline__ float gelu_exact(float v) {
    return 0.5f * v * (1.0f + erff(v * 0.70710678118654752f));
}
__device__ __forceinline__ float sigmoidf_(float v) {
    return 1.0f / (1.0f + __expf(-v));
}
__device__ __forceinline__ void split_bf16(float v, __nv_bfloat16& h, __nv_bfloat16& l) {
    h = __float2bfloat16_rn(v);
    l = __float2bfloat16_rn(v - __bfloat162float(h));
}

// ------------------------- row stats (mean, inv-std) [+ optional split] -----
template <int EPT, bool SPLIT>
__global__ __launch_bounds__(256) void stats_split_kernel(
    const float* __restrict__ in, float* __restrict__ muO, float* __restrict__ ivO,
    __nv_bfloat16* __restrict__ oH, __nv_bfloat16* __restrict__ oL, int D)
{
    const int row = blockIdx.x;
    const int tid = threadIdx.x;
    const float* rp = in + (size_t)row * D;

    float v[EPT];
    float s = 0.f;
#pragma unroll
    for (int e = 0; e < EPT; e++) { v[e] = rp[tid + e * 256]; s += v[e]; }

    __shared__ float red[8];
    __shared__ float sMean, sVar;
#pragma unroll
    for (int o = 16; o > 0; o >>= 1) s += __shfl_down_sync(0xffffffffu, s, o);
    if ((tid & 31) == 0) red[tid >> 5] = s;
    __syncthreads();
    if (tid < 8) {
        float w = red[tid];
#pragma unroll
        for (int o = 4; o > 0; o >>= 1) w += __shfl_down_sync(0xffu, w, o);
        if (tid == 0) sMean = w / (float)D;
    }
    __syncthreads();
    const float mean = sMean;

    float q = 0.f;
#pragma unroll
    for (int e = 0; e < EPT; e++) { float d = v[e] - mean; q += d * d; }
#pragma unroll
    for (int o = 16; o > 0; o >>= 1) q += __shfl_down_sync(0xffffffffu, q, o);
    if ((tid & 31) == 0) red[tid >> 5] = q;
    __syncthreads();
    if (tid < 8) {
        float w = red[tid];
#pragma unroll
        for (int o = 4; o > 0; o >>= 1) w += __shfl_down_sync(0xffu, w, o);
        if (tid == 0) sVar = w / (float)D;
    }
    __syncthreads();
    if (tid == 0) { muO[row] = mean; ivO[row] = rsqrtf(sVar + 1e-6f); }

    if (SPLIT) {
        const size_t rb = (size_t)row * D;
#pragma unroll
        for (int e = 0; e < EPT; e++) {
            int c = tid + e * 256;
            __nv_bfloat16 h, l;
            split_bf16(v[e], h, l);
            oH[rb + c] = h; oL[rb + c] = l;
        }
    }
}

// ------------------------- TT operator materialization ----------------------
__global__ __launch_bounds__(256) void build_a01_kernel(
    const float* __restrict__ c0, const float* __restrict__ c1,
    float* __restrict__ a01)
{
    int idx = blockIdx.x * 256 + threadIdx.x;   // 131072
    int s = idx & 15, y = (idx >> 4) & 15, b = (idx >> 8) & 7;
    int x = (idx >> 11) & 7, a = idx >> 14;
    float acc = 0.f;
#pragma unroll
    for (int r = 0; r < 16; r++)
        acc += c0[a * 128 + x * 16 + r] * c1[((r * 8 + b) * 16 + y) * 16 + s];
    a01[idx] = acc;
}

__global__ __launch_bounds__(256) void build_wttT_kernel(
    const float* __restrict__ a01, const float* __restrict__ c2,
    __nv_bfloat16* __restrict__ wH, __nv_bfloat16* __restrict__ wL)
{
    int idx = blockIdx.x * 256 + threadIdx.x;   // 4096*1024
    int in  = idx & 1023;
    int out = idx >> 10;
    int z = out & 31, y = (out >> 5) & 15, x = out >> 9;
    int c = in & 15,  b = (in >> 4) & 7,   a = in >> 7;
    const float* ap = a01 + (((a * 8 + x) * 8 + b) * 16 + y) * 16;
    float acc = 0.f;
#pragma unroll
    for (int s = 0; s < 16; s++)
        acc += ap[s] * c2[(s * 16 + c) * 32 + z];
    __nv_bfloat16 h, l;
    split_bf16(acc, h, l);
    wH[idx] = h; wL[idx] = l;
}

// ------------------------- batched weight transpose + split ------------------
// z=0: dense weight scaled by gamma[k]; z=1: gate weight unscaled.
__global__ __launch_bounds__(256) void transpose_split2_kernel(
    const float* __restrict__ in0, const float* __restrict__ gamma,
    __nv_bfloat16* __restrict__ o0H, __nv_bfloat16* __restrict__ o0L,
    const float* __restrict__ in1, __nv_bfloat16* __restrict__ o1H,
    __nv_bfloat16* __restrict__ o1L, int K, int N)
{
    const bool zz = (blockIdx.z != 0);
    const float* in = zz ? in1 : in0;
    __nv_bfloat16* oH = zz ? o1H : o0H;
    __nv_bfloat16* oL = zz ? o1L : o0L;
    __shared__ float tile[32][33];
    int n0 = blockIdx.x * 32, k0 = blockIdx.y * 32;
    int tx = threadIdx.x & 31, ty = threadIdx.x >> 5;
#pragma unroll
    for (int i = 0; i < 4; i++)
        tile[ty + i * 8][tx] = in[(size_t)(k0 + ty + i * 8) * N + n0 + tx];
    __syncthreads();
    const float gk = zz ? 1.f : gamma[k0 + tx];
#pragma unroll
    for (int i = 0; i < 4; i++) {
        float v = tile[tx][ty + i * 8] * gk;
        __nv_bfloat16 h, l;
        split_bf16(v, h, l);
        size_t o = (size_t)(n0 + ty + i * 8) * K + k0 + tx;
        oH[o] = h; oL[o] = l;
    }
}

// ------------------------- parallel column sums (two-pass) ------------------
// Pass 1: each block reduces a 128(K) x 256(N) panel -> partials [KCH][N].
__global__ __launch_bounds__(256) void colsum_part_kernel(
    const float* __restrict__ W, const float* __restrict__ gamma,
    const float* __restrict__ beta, float* __restrict__ pGW,
    float* __restrict__ pBW, int N)
{
    const int n  = blockIdx.x * 256 + threadIdx.x;
    const int k0 = blockIdx.y * 128;
    float sg = 0.f, sb = 0.f;
#pragma unroll 8
    for (int i = 0; i < 128; i++) {
        float w = W[(size_t)(k0 + i) * N + n];
        sg += gamma[k0 + i] * w;
        sb += beta[k0 + i] * w;
    }
    pGW[blockIdx.y * N + n] = sg;
    pBW[blockIdx.y * N + n] = sb;
}
// Pass 2: sum KCH partials per column (fixed order -> deterministic).
__global__ __launch_bounds__(256) void colsum_reduce_kernel(
    const float* __restrict__ pGW, const float* __restrict__ pBW,
    float* __restrict__ vGW, float* __restrict__ vBW, int N, int KCH)
{
    const int n = blockIdx.x * 256 + threadIdx.x;
    float sg = 0.f, sb = 0.f;
    for (int c = 0; c < KCH; c++) { sg += pGW[c * N + n]; sb += pBW[c * N + n]; }
    vGW[n] = sg; vBW[n] = sb;
}

// ------------------------- streaming combine: out = g*h + (1-g)*r -----------
__global__ __launch_bounds__(256) void combine_kernel(
    const float* __restrict__ g, const float* __restrict__ h,
    const float* __restrict__ r, float* __restrict__ out, int n4)
{
    int i = blockIdx.x * 256 + threadIdx.x;
    if (i < n4) {
        float4 gv = ((const float4*)g)[i];
        float4 hv = ((const float4*)h)[i];
        float4 rv = ((const float4*)r)[i];
        float4 o;
        o.x = gv.x * hv.x + (1.f - gv.x) * rv.x;
        o.y = gv.y * hv.y + (1.f - gv.y) * rv.y;
        o.z = gv.z * hv.z + (1.f - gv.z) * rv.z;
        o.w = gv.w * hv.w + (1.f - gv.w) * rv.w;
        ((float4*)out)[i] = o;
    }
}

// ------------------------- core mainloop (shared) ----------------------------
__device__ __forceinline__ void load_stage4(
    uint32_t sbase,
    const __nv_bfloat16* __restrict__ Ah, const __nv_bfloat16* __restrict__ Al,
    const __nv_bfloat16* __restrict__ Bh, const __nv_bfloat16* __restrict__ Bl,
    int aRow0, int bRow0, int K, int k0, int tid)
{
#pragma unroll
    for (int i = 0; i < 4; i++) {
        int idx = tid + i * NTHR;
        int r = idx >> 2, c = idx & 3;
        uint32_t so = swz(r, c);
        size_t ga = (size_t)(aRow0 + r) * K + k0 + c * 8;
        size_t gb = (size_t)(bRow0 + r) * K + k0 + c * 8;
        cp16(sbase + OFF_AH + so, Ah + ga);
        cp16(sbase + OFF_AL + so, Al + ga);
        cp16(sbase + OFF_BH + so, Bh + gb);
        cp16(sbase + OFF_BL + so, Bl + gb);
    }
}

// mainloop producing acc[4][8][4] for one 128x128 tile; warp tile 64x64.
__device__ __forceinline__ void gemm_mainloop(
    uint32_t sm, float acc[4][8][4],
    const __nv_bfloat16* __restrict__ Ah, const __nv_bfloat16* __restrict__ Al,
    const __nv_bfloat16* __restrict__ Bh, const __nv_bfloat16* __restrict__ Bl,
    int blockM, int blockN, int K, int tid, int lane, int wm, int wn)
{
    const int nk = K / BK;
#pragma unroll
    for (int s = 0; s < STAGES - 1; s++) {
        load_stage4(sm + s * STAGE_BYTES, Ah, Al, Bh, Bl, blockM, blockN, K, s * BK, tid);
        CP_COMMIT();
    }
    const int aRow = lane & 15;
    const int aHi  = lane >> 4;
    const int bRow = wn + (lane & 7) + ((lane >> 4) << 3);
    const int bHi  = (lane >> 3) & 1;
    const int sA = ((aRow >> 1) & 3);
    const int sB = ((bRow >> 1) & 3);   // invariant under +16 row steps

    for (int t = 0; t < nk; t++) {
        CP_WAIT1();
        __syncthreads();
        const int pf = t + STAGES - 1;
        const uint32_t sb = sm + (t % STAGES) * STAGE_BYTES;

#pragma unroll
        for (int ks = 0; ks < 2; ks++) {
            const uint32_t aChunk = (uint32_t)(((ks * 2 + aHi) ^ sA) << 4);
            const uint32_t bChunk = (uint32_t)(((ks * 2 + bHi) ^ sB) << 4);
            uint32_t ah[4][4], al[4][4];
#pragma unroll
            for (int mt = 0; mt < 4; mt++) {
                const uint32_t ra = (uint32_t)((wm + mt * 16 + aRow) * 64) + aChunk;
                ldmx4(ah[mt], sb + OFF_AH + ra);
                ldmx4(al[mt], sb + OFF_AL + ra);
            }
            if (ks == 0) {
                if (pf < nk)
                    load_stage4(sm + (pf % STAGES) * STAGE_BYTES, Ah, Al, Bh, Bl,
                                blockM, blockN, K, pf * BK, tid);
                CP_COMMIT();
            }
            uint32_t bh[2][4], bl[2][4];
            {
                const uint32_t rg = (uint32_t)(bRow * 64) + bChunk;
                ldmx4(bh[0], sb + OFF_BH + rg);
                ldmx4(bl[0], sb + OFF_BL + rg);
            }
#pragma unroll
            for (int g = 0; g < 4; g++) {
                const int cur = g & 1;
                const int nxt = cur ^ 1;
                if (g < 3) {
                    const uint32_t rg = (uint32_t)((bRow + (g + 1) * 16) * 64) + bChunk;
                    ldmx4(bh[nxt], sb + OFF_BH + rg);
                    ldmx4(bl[nxt], sb + OFF_BL + rg);
                }
#pragma unroll
                for (int mt = 0; mt < 4; mt++) mma_bf16(acc[mt][2 * g + 0], ah[mt], bh[cur] + 0);
#pragma unroll
                for (int mt = 0; mt < 4; mt++) mma_bf16(acc[mt][2 * g + 1], ah[mt], bh[cur] + 2);
#pragma unroll
                for (int mt = 0; mt < 4; mt++) mma_bf16(acc[mt][2 * g + 0], ah[mt], bl[cur] + 0);
#pragma unroll
                for (int mt = 0; mt < 4; mt++) mma_bf16(acc[mt][2 * g + 1], ah[mt], bl[cur] + 2);
#pragma unroll
                for (int mt = 0; mt < 4; mt++) mma_bf16(acc[mt][2 * g + 0], al[mt], bh[cur] + 0);
#pragma unroll
                for (int mt = 0; mt < 4; mt++) mma_bf16(acc[mt][2 * g + 1], al[mt], bh[cur] + 2);
            }
        }
    }
    CP_WAIT0();
}

// ------------------------- GEMM kernels --------------------------------------
// OP_LNGELU: v = iv[m]*acc - mu[m]*iv[m]*vGW[n] + vBW[n] + bias[n]; gelu(v)
template <int OP, bool WF32, bool WSPLIT>
__global__ __launch_bounds__(NTHR, 2) void mma_gemm_kernel(
    const __nv_bfloat16* __restrict__ Ah, const __nv_bfloat16* __restrict__ Al,
    const __nv_bfloat16* __restrict__ Bh, const __nv_bfloat16* __restrict__ Bl,
    const float* __restrict__ bias, const float* __restrict__ Hm,
    const float* __restrict__ Rm,
    const float* __restrict__ mu, const float* __restrict__ iv,
    const float* __restrict__ vGW, const float* __restrict__ vBW,
    float* __restrict__ CF, __nv_bfloat16* __restrict__ CH,
    __nv_bfloat16* __restrict__ CL, int M, int N, int K)
{
    extern __shared__ char smem[];
    const uint32_t sm = smem_u32(smem);
    const int tid  = threadIdx.x;
    const int lane = tid & 31;
    const int wid  = tid >> 5;
    const int blockM = blockIdx.x * BM;
    const int blockN = blockIdx.y * BN;
    const int wm = (wid >> 1) * 64;
    const int wn = (wid & 1) * 64;

    float acc[4][8][4];
#pragma unroll
    for (int i = 0; i < 4; i++)
#pragma unroll
        for (int j = 0; j < 8; j++)
#pragma unroll
            for (int e = 0; e < 4; e++) acc[i][j][e] = 0.f;

    gemm_mainloop(sm, acc, Ah, Al, Bh, Bl, blockM, blockN, K, tid, lane, wm, wn);

    const int r0 = lane >> 2;
    const int c0 = (lane & 3) * 2;
#pragma unroll
    for (int mt = 0; mt < 4; mt++) {
#pragma unroll
        for (int half = 0; half < 2; half++) {
            const int m = blockM + wm + mt * 16 + r0 + half * 8;
            const size_t base = (size_t)m * N;
            float iv_m = 0.f, miv = 0.f;
            if (OP == OP_LNGELU) { iv_m = iv[m]; miv = mu[m] * iv_m; }
#pragma unroll
            for (int nt = 0; nt < 8; nt++) {
                const int n = blockN + wn + nt * 8 + c0;
                float v0 = acc[mt][nt][half * 2 + 0];
                float v1 = acc[mt][nt][half * 2 + 1];
                if (OP == OP_GELU) {
                    v0 = gelu_exact(v0 + bias[n]);
                    v1 = gelu_exact(v1 + bias[n + 1]);
                } else if (OP == OP_LNGELU) {
                    v0 = gelu_exact(iv_m * v0 - miv * vGW[n]     + vBW[n]     + bias[n]);
                    v1 = gelu_exact(iv_m * v1 - miv * vGW[n + 1] + vBW[n + 1] + bias[n + 1]);
                } else if (OP == OP_GATE) {
                    float2 hh = *(const float2*)(Hm + base + n);
                    float2 rr = *(const float2*)(Rm + base + n);
                    float g0 = sigmoidf_(v0 + bias[n]);
                    float g1 = sigmoidf_(v1 + bias[n + 1]);
                    v0 = g0 * hh.x + (1.f - g0) * rr.x;
                    v1 = g1 * hh.y + (1.f - g1) * rr.y;
                }
                if (WF32) *(float2*)(CF + base + n) = make_float2(v0, v1);
                if (WSPLIT) {
                    __nv_bfloat16 hA, lA, hB, lB;
                    split_bf16(v0, hA, lA);
                    split_bf16(v1, hB, lB);
                    __nv_bfloat162 ph; ph.x = hA; ph.y = hB;
                    __nv_bfloat162 pl; pl.x = lA; pl.y = lB;
                    *(__nv_bfloat162*)(CH + base + n) = ph;
                    *(__nv_bfloat162*)(CL + base + n) = pl;
                }
            }
        }
    }
}

// merged post GEMM, shared A = t-split:
//   z=0: B=(gamma.*Wd)^T -> h2 = gelu(LN-corrected acc + db)
//   z=1: B=Wg^T          -> g  = sigmoid(acc + gb)
__global__ __launch_bounds__(NTHR, 2) void post_merged_kernel(
    const __nv_bfloat16* __restrict__ AH, const __nv_bfloat16* __restrict__ AL,
    const __nv_bfloat16* __restrict__ BdH, const __nv_bfloat16* __restrict__ BdL,
    const __nv_bfloat16* __restrict__ BgH, const __nv_bfloat16* __restrict__ BgL,
    const float* __restrict__ mu, const float* __restrict__ iv,
    const float* __restrict__ vGW, const float* __restrict__ vBW,
    const float* __restrict__ db, const float* __restrict__ gbv,
    float* __restrict__ h2, float* __restrict__ gbuf, int M, int N, int K)
{
    extern __shared__ char smem[];
    const uint32_t sm = smem_u32(smem);
    const int tid  = threadIdx.x;
    const int lane = tid & 31;
    const int wid  = tid >> 5;
    const int blockM = blockIdx.x * BM;
    const int blockN = blockIdx.y * BN;
    const int z = blockIdx.z;
    const int wm = (wid >> 1) * 64;
    const int wn = (wid & 1) * 64;

    const __nv_bfloat16* Bh = z ? BgH : BdH;
    const __nv_bfloat16* Bl = z ? BgL : BdL;
    const float* bias = z ? gbv : db;
    float* CF = z ? gbuf : h2;

    float acc[4][8][4];
#pragma unroll
    for (int i = 0; i < 4; i++)
#pragma unroll
        for (int j = 0; j < 8; j++)
#pragma unroll
            for (int e = 0; e < 4; e++) acc[i][j][e] = 0.f;

    gemm_mainloop(sm, acc, AH, AL, Bh, Bl, blockM, blockN, K, tid, lane, wm, wn);

    const int r0 = lane >> 2;
    const int c0 = (lane & 3) * 2;
#pragma unroll
    for (int mt = 0; mt < 4; mt++) {
#pragma unroll
        for (int half = 0; half < 2; half++) {
            const int m = blockM + wm + mt * 16 + r0 + half * 8;
            const size_t base = (size_t)m * N;
            float iv_m = 0.f, miv = 0.f;
            if (z == 0) { iv_m = iv[m]; miv = mu[m] * iv_m; }
#pragma unroll
            for (int nt = 0; nt < 8; nt++) {
                const int n = blockN + wn + nt * 8 + c0;
                float v0 = acc[mt][nt][half * 2 + 0];
                float v1 = acc[mt][nt][half * 2 + 1];
                if (z == 0) {
                    v0 = gelu_exact(iv_m * v0 - miv * vGW[n]     + vBW[n]     + bias[n]);
                    v1 = gelu_exact(iv_m * v1 - miv * vGW[n + 1] + vBW[n + 1] + bias[n + 1]);
                } else {
                    v0 = sigmoidf_(v0 + bias[n]);
                    v1 = sigmoidf_(v1 + bias[n + 1]);
                }
                *(float2*)(CF + base + n) = make_float2(v0, v1);
            }
        }
    }
}

// ------------------------- launch ------------------------------------------
extern "C" void kernel_launch(void* const* d_in, const int* in_sizes, int n_in,
                              void* d_out, int out_size)
{
    const float* x      = (const float*)d_in[0];
    const float* preG   = (const float*)d_in[1];
    const float* preB   = (const float*)d_in[2];
    const float* preDw  = (const float*)d_in[3];
    const float* preDb  = (const float*)d_in[4];
    const float* preGw  = (const float*)d_in[5];
    const float* preGb  = (const float*)d_in[6];
    const float* core0  = (const float*)d_in[7];
    const float* core1  = (const float*)d_in[8];
    const float* core2  = (const float*)d_in[9];
    const float* postG  = (const float*)d_in[10];
    const float* postB  = (const float*)d_in[11];
    const float* postDw = (const float*)d_in[12];
    const float* postDb = (const float*)d_in[13];
    const float* postGw = (const float*)d_in[14];
    const float* postGb = (const float*)d_in[15];
    float* out = (float*)d_out;

    float *h1, *t, *h2, *gbuf, *a01;
    float *mu1, *iv1, *mu2, *iv2, *vGW1, *vBW1, *vGW2, *vBW2, *pGW, *pBW;
    cudaGetSymbolAddress((void**)&h1,   g_h1);
    cudaGetSymbolAddress((void**)&t,    g_t);
    cudaGetSymbolAddress((void**)&h2,   g_h2);
    cudaGetSymbolAddress((void**)&gbuf, g_gb);
    cudaGetSymbolAddress((void**)&a01,  g_a01);
    cudaGetSymbolAddress((void**)&mu1,  g_mu1);
    cudaGetSymbolAddress((void**)&iv1,  g_iv1);
    cudaGetSymbolAddress((void**)&mu2,  g_mu2);
    cudaGetSymbolAddress((void**)&iv2,  g_iv2);
    cudaGetSymbolAddress((void**)&vGW1, g_vGW1);
    cudaGetSymbolAddress((void**)&vBW1, g_vBW1);
    cudaGetSymbolAddress((void**)&vGW2, g_vGW2);
    cudaGetSymbolAddress((void**)&vBW2, g_vBW2);
    cudaGetSymbolAddress((void**)&pGW,  g_pGW);
    cudaGetSymbolAddress((void**)&pBW,  g_pBW);

    __nv_bfloat16 *xH, *xL, *hpreH, *hpreL, *tH, *tL;
    __nv_bfloat16 *preDwTH, *preDwTL, *preGwTH, *preGwTL;
    __nv_bfloat16 *wttTH, *wttTL, *postDwTH, *postDwTL, *postGwTH, *postGwTL;
    cudaGetSymbolAddress((void**)&xH,    g_xH);    cudaGetSymbolAddress((void**)&xL,    g_xL);
    cudaGetSymbolAddress((void**)&hpreH, g_hpreH); cudaGetSymbolAddress((void**)&hpreL, g_hpreL);
    cudaGetSymbolAddress((void**)&tH,    g_tH);    cudaGetSymbolAddress((void**)&tL,    g_tL);
    cudaGetSymbolAddress((void**)&preDwTH,  g_preDwTH);  cudaGetSymbolAddress((void**)&preDwTL,  g_preDwTL);
    cudaGetSymbolAddress((void**)&preGwTH,  g_preGwTH);  cudaGetSymbolAddress((void**)&preGwTL,  g_preGwTL);
    cudaGetSymbolAddress((void**)&wttTH,    g_wttTH);    cudaGetSymbolAddress((void**)&wttTL,    g_wttTL);
    cudaGetSymbolAddress((void**)&postDwTH, g_postDwTH); cudaGetSymbolAddress((void**)&postDwTL, g_postDwTL);
    cudaGetSymbolAddress((void**)&postGwTH, g_postGwTH); cudaGetSymbolAddress((void**)&postGwTL, g_postGwTL);

    cudaFuncSetAttribute(mma_gemm_kernel<OP_LNGELU, true, false>,
                         cudaFuncAttributeMaxDynamicSharedMemorySize, GEMM_SMEM);
    cudaFuncSetAttribute(mma_gemm_kernel<OP_GATE, false, true>,
                         cudaFuncAttributeMaxDynamicSharedMemorySize, GEMM_SMEM);
    cudaFuncSetAttribute(mma_gemm_kernel<OP_NONE, true, true>,
                         cudaFuncAttributeMaxDynamicSharedMemorySize, GEMM_SMEM);
    cudaFuncSetAttribute(post_merged_kernel,
                         cudaFuncAttributeMaxDynamicSharedMemorySize, GEMM_SMEM);

    // --- operator prep (independent of x) ---
    build_a01_kernel<<<131072 / 256, 256>>>(core0, core1, a01);
    build_wttT_kernel<<<(DIN * DOUT) / 256, 256>>>(a01, core2, wttTH, wttTL);
    transpose_split2_kernel<<<dim3(DIN / 32, DIN / 32, 2), 256>>>(
        preDw, preG, preDwTH, preDwTL, preGw, preGwTH, preGwTL, DIN, DIN);
    transpose_split2_kernel<<<dim3(DOUT / 32, DOUT / 32, 2), 256>>>(
        postDw, postG, postDwTH, postDwTL, postGw, postGwTH, postGwTL, DOUT, DOUT);
    colsum_part_kernel<<<dim3(DIN / 256, DIN / 128), 256>>>(preDw, preG, preB, pGW, pBW, DIN);
    colsum_reduce_kernel<<<DIN / 256, 256>>>(pGW, pBW, vGW1, vBW1, DIN, DIN / 128);
    colsum_part_kernel<<<dim3(DOUT / 256, DOUT / 128), 256>>>(postDw, postG, postB, pGW, pBW, DOUT);
    colsum_reduce_kernel<<<DOUT / 256, 256>>>(pGW, pBW, vGW2, vBW2, DOUT, DOUT / 128);

    // --- pre block: stats(+x split), LN-folded dense, fused gate ---
    stats_split_kernel<DIN / 256, true><<<NTOK, 256>>>(x, mu1, iv1, xH, xL, DIN);
    mma_gemm_kernel<OP_LNGELU, true, false><<<dim3(NTOK / BM, DIN / BN), NTHR, GEMM_SMEM>>>(
        xH, xL, preDwTH, preDwTL, preDb, nullptr, nullptr,
        mu1, iv1, vGW1, vBW1, h1, nullptr, nullptr, NTOK, DIN, DIN);
    mma_gemm_kernel<OP_GATE, false, true><<<dim3(NTOK / BM, DIN / BN), NTHR, GEMM_SMEM>>>(
        xH, xL, preGwTH, preGwTL, preGb, h1, x,
        nullptr, nullptr, nullptr, nullptr, nullptr, hpreH, hpreL, NTOK, DIN, DIN);

    // --- TT contraction ---
    mma_gemm_kernel<OP_NONE, true, true><<<dim3(NTOK / BM, DOUT / BN), NTHR, GEMM_SMEM>>>(
        hpreH, hpreL, wttTH, wttTL, nullptr, nullptr, nullptr,
        nullptr, nullptr, nullptr, nullptr, t, tH, tL, NTOK, DOUT, DIN);

    // --- post block: stats only, merged dense+gate sharing A=t-split, combine ---
    stats_split_kernel<DOUT / 256, false><<<NTOK, 256>>>(t, mu2, iv2, nullptr, nullptr, DOUT);
    post_merged_kernel<<<dim3(NTOK / BM, DOUT / BN, 2), NTHR, GEMM_SMEM>>>(
        tH, tL, postDwTH, postDwTL, postGwTH, postGwTL,
        mu2, iv2, vGW2, vBW2, postDb, postGb, h2, gbuf, NTOK, DOUT, DOUT);
    combine_kernel<<<(NTOK * DOUT / 4 + 255) / 256, 256>>>(
        gbuf, h2, t, out, NTOK * DOUT / 4);
}

// round 17
// speedup vs baseline: 1.6182x; 1.0531x over previous
#include <cuda_runtime.h>
#include <cuda_bf16.h>
#include <math.h>
#include <stdint.h>

// ---------------------------------------------------------------------------
// HybridTTLayer via mma.sync bf16 tensor cores (plain sm_100 target).
// fp32 emulated as bf16 hi+lo split, 3-product MMA.
// R17 = R14 (best: 2484us; CTA 128x128, 4 warps, 64x64 warp tile, BK=32,
// 3-stage cp.async, 2 CTAs/SM, merged post GEMM + combine) with vectorized
// bf16x2 stores in the elementwise kernels (transpose/split, wttT build,
// layernorm split) which profiled at ~51% DRAM due to 2B scattered stores.
// ---------------------------------------------------------------------------

#define NTOK   4096
#define DIN    1024
#define DOUT   4096

#define OP_NONE 0
#define OP_GELU 1
#define OP_GATE 2

// GEMM tiling
#define BM 128
#define BN 128
#define BK 32
#define NTHR 128
#define STAGES 3
#define OFF_AH 0
#define OFF_AL 8192
#define OFF_BH 16384
#define OFF_BL 24576
#define STAGE_BYTES 32768
#define GEMM_SMEM (STAGES * STAGE_BYTES)   // 98304 -> 2 CTAs/SM

// swizzled byte offset of 16B chunk c (0..3) in row r (64B rows)
__device__ __forceinline__ uint32_t swz(int r, int c) {
    return (uint32_t)(r * 64 + ((c ^ ((r >> 1) & 3)) << 4));
}

// ------------------------- scratch (static device memory) ------------------
__device__ float g_h1 [NTOK * DIN];
__device__ float g_t  [NTOK * DOUT];
__device__ float g_h2 [NTOK * DOUT];
__device__ float g_gb [NTOK * DOUT];      // post gate sigmoid buffer
__device__ float g_a01[8 * 8 * 8 * 16 * 16];
__device__ __nv_bfloat16 g_xH   [NTOK * DIN],  g_xL   [NTOK * DIN];
__device__ __nv_bfloat16 g_ln1H [NTOK * DIN],  g_ln1L [NTOK * DIN];
__device__ __nv_bfloat16 g_hpreH[NTOK * DIN],  g_hpreL[NTOK * DIN];
__device__ __nv_bfloat16 g_tH   [NTOK * DOUT], g_tL   [NTOK * DOUT];
__device__ __nv_bfloat16 g_ln2H [NTOK * DOUT], g_ln2L [NTOK * DOUT];
__device__ __nv_bfloat16 g_preDwTH [DIN * DIN],   g_preDwTL [DIN * DIN];
__device__ __nv_bfloat16 g_preGwTH [DIN * DIN],   g_preGwTL [DIN * DIN];
__device__ __nv_bfloat16 g_wttTH   [DOUT * DIN],  g_wttTL   [DOUT * DIN];
__device__ __nv_bfloat16 g_postDwTH[DOUT * DOUT], g_postDwTL[DOUT * DOUT];
__device__ __nv_bfloat16 g_postGwTH[DOUT * DOUT], g_postGwTL[DOUT * DOUT];

// ------------------------- helpers -----------------------------------------
__device__ __forceinline__ uint32_t smem_u32(const void* p) {
    uint32_t a;
    asm("{ .reg .u64 t; cvta.to.shared.u64 t, %1; cvt.u32.u64 %0, t; }"
        : "=r"(a) : "l"(p));
    return a;
}
__device__ __forceinline__ void cp16(uint32_t s, const void* g) {
    asm volatile("cp.async.cg.shared.global [%0], [%1], 16;" :: "r"(s), "l"(g));
}
#define CP_COMMIT() asm volatile("cp.async.commit_group;")
#define CP_WAIT1()  asm volatile("cp.async.wait_group 1;")
#define CP_WAIT0()  asm volatile("cp.async.wait_group 0;")

__device__ __forceinline__ void ldmx4(uint32_t* r, uint32_t a) {
    asm volatile("ldmatrix.sync.aligned.m8n8.x4.shared.b16 {%0,%1,%2,%3}, [%4];"
        : "=r"(r[0]), "=r"(r[1]), "=r"(r[2]), "=r"(r[3]) : "r"(a));
}
__device__ __forceinline__ void mma_bf16(float* d, const uint32_t* a, const uint32_t* b) {
    asm volatile("mma.sync.aligned.m16n8k16.row.col.f32.bf16.bf16.f32 "
        "{%0,%1,%2,%3}, {%4,%5,%6,%7}, {%8,%9}, {%0,%1,%2,%3};"
        : "+f"(d[0]), "+f"(d[1]), "+f"(d[2]), "+f"(d[3])
        : "r"(a[0]), "r"(a[1]), "r"(a[2]), "r"(a[3]), "r"(b[0]), "r"(b[1]));
}
__device__ __forceinline__ float gelu_exact(float v) {
    return 0.5f * v * (1.0f + erff(v * 0.70710678118654752f));
}
__device__ __forceinline__ float sigmoidf_(float v) {
    return 1.0f / (1.0f + __expf(-v));
}
__device__ __forceinline__ void split_bf16(float v, __nv_bfloat16& h, __nv_bfloat16& l) {
    h = __float2bfloat16_rn(v);
    l = __float2bfloat16_rn(v - __bfloat162float(h));
}
__device__ __forceinline__ __nv_bfloat162 pack2h(float a, float b, float& la, float& lb) {
    __nv_bfloat16 ha = __float2bfloat16_rn(a);
    __nv_bfloat16 hb = __float2bfloat16_rn(b);
    la = a - __bfloat162float(ha);
    lb = b - __bfloat162float(hb);
    __nv_bfloat162 p; p.x = ha; p.y = hb;
    return p;
}
__device__ __forceinline__ __nv_bfloat162 pack2(float a, float b) {
    __nv_bfloat162 p;
    p.x = __float2bfloat16_rn(a);
    p.y = __float2bfloat16_rn(b);
    return p;
}

// ------------------------- layernorm (vectorized bf16x2 IO) ------------------
// EPT2 = D/512 float2-pairs per thread (256 threads)
template <int EPT2, bool SPLIT_IN>
__global__ __launch_bounds__(256) void layernorm_split_kernel(
    const float* __restrict__ in, const float* __restrict__ gamma,
    const float* __restrict__ beta,
    __nv_bfloat16* __restrict__ oH, __nv_bfloat16* __restrict__ oL,
    __nv_bfloat16* __restrict__ iH, __nv_bfloat16* __restrict__ iL, int D)
{
    const int row = blockIdx.x;
    const int tid = threadIdx.x;
    const float2* rp = (const float2*)(in + (size_t)row * D);

    float2 v[EPT2];
    float s = 0.f;
#pragma unroll
    for (int e = 0; e < EPT2; e++) { v[e] = rp[tid + e * 256]; s += v[e].x + v[e].y; }

    __shared__ float red[8];
    __shared__ float sMean, sVar;
#pragma unroll
    for (int o = 16; o > 0; o >>= 1) s += __shfl_down_sync(0xffffffffu, s, o);
    if ((tid & 31) == 0) red[tid >> 5] = s;
    __syncthreads();
    if (tid < 8) {
        float w = red[tid];
#pragma unroll
        for (int o = 4; o > 0; o >>= 1) w += __shfl_down_sync(0xffu, w, o);
        if (tid == 0) sMean = w / (float)D;
    }
    __syncthreads();
    const float mean = sMean;

    float q = 0.f;
#pragma unroll
    for (int e = 0; e < EPT2; e++) {
        float dx = v[e].x - mean, dy = v[e].y - mean;
        q += dx * dx + dy * dy;
    }
#pragma unroll
    for (int o = 16; o > 0; o >>= 1) q += __shfl_down_sync(0xffffffffu, q, o);
    if ((tid & 31) == 0) red[tid >> 5] = q;
    __syncthreads();
    if (tid < 8) {
        float w = red[tid];
#pragma unroll
        for (int o = 4; o > 0; o >>= 1) w += __shfl_down_sync(0xffu, w, o);
        if (tid == 0) sVar = w / (float)D;
    }
    __syncthreads();
    const float inv = rsqrtf(sVar + 1e-6f);

    const size_t rb2 = (size_t)row * (D >> 1);
    __nv_bfloat162* oH2 = (__nv_bfloat162*)oH;
    __nv_bfloat162* oL2 = (__nv_bfloat162*)oL;
    __nv_bfloat162* iH2 = (__nv_bfloat162*)iH;
    __nv_bfloat162* iL2 = (__nv_bfloat162*)iL;
    const float2* g2 = (const float2*)gamma;
    const float2* b2 = (const float2*)beta;
#pragma unroll
    for (int e = 0; e < EPT2; e++) {
        int c = tid + e * 256;
        float2 gg = g2[c], bb = b2[c];
        float o0 = (v[e].x - mean) * inv * gg.x + bb.x;
        float o1 = (v[e].y - mean) * inv * gg.y + bb.y;
        float l0, l1;
        oH2[rb2 + c] = pack2h(o0, o1, l0, l1);
        oL2[rb2 + c] = pack2(l0, l1);
        if (SPLIT_IN) {
            iH2[rb2 + c] = pack2h(v[e].x, v[e].y, l0, l1);
            iL2[rb2 + c] = pack2(l0, l1);
        }
    }
}

// ------------------------- TT operator materialization ----------------------
__global__ __launch_bounds__(256) void build_a01_kernel(
    const float* __restrict__ c0, const float* __restrict__ c1,
    float* __restrict__ a01)
{
    int idx = blockIdx.x * 256 + threadIdx.x;   // 131072
    int s = idx & 15, y = (idx >> 4) & 15, b = (idx >> 8) & 7;
    int x = (idx >> 11) & 7, a = idx >> 14;
    float acc = 0.f;
#pragma unroll
    for (int r = 0; r < 16; r++)
        acc += c0[a * 128 + x * 16 + r] * c1[((r * 8 + b) * 16 + y) * 16 + s];
    a01[idx] = acc;
}

// wttT[out][in] bf16 hi/lo, paired writes (each thread does 2 consecutive in)
__global__ __launch_bounds__(256) void build_wttT_kernel(
    const float* __restrict__ a01, const float* __restrict__ c2,
    __nv_bfloat16* __restrict__ wH, __nv_bfloat16* __restrict__ wL)
{
    int p = blockIdx.x * 256 + threadIdx.x;     // 2M pairs
    int out = p >> 9;                            // 1024 in / 2 = 512 pairs per out
    int inp = (p & 511) * 2;
    int z = out & 31, y = (out >> 5) & 15, x = out >> 9;
    float vv[2];
#pragma unroll
    for (int j = 0; j < 2; j++) {
        int in = inp + j;
        int c = in & 15, b = (in >> 4) & 7, a = in >> 7;
        const float* ap = a01 + (((a * 8 + x) * 8 + b) * 16 + y) * 16;
        float acc = 0.f;
#pragma unroll
        for (int s = 0; s < 16; s++)
            acc += ap[s] * c2[(s * 16 + c) * 32 + z];
        vv[j] = acc;
    }
    float l0, l1;
    ((__nv_bfloat162*)wH)[p] = pack2h(vv[0], vv[1], l0, l1);
    ((__nv_bfloat162*)wL)[p] = pack2(l0, l1);
}

// ------------------------- batched transpose + split (bf16x2 stores) ---------
// Panel: 64 k-rows x 32 n-cols. Writes out[n][k] as bf16x2 (k-pairs).
__global__ __launch_bounds__(256) void transpose_split2_kernel(
    const float* __restrict__ in0, __nv_bfloat16* __restrict__ o0H,
    __nv_bfloat16* __restrict__ o0L,
    const float* __restrict__ in1, __nv_bfloat16* __restrict__ o1H,
    __nv_bfloat16* __restrict__ o1L, int K, int N)
{
    const bool zz = (blockIdx.z != 0);
    const float* in = zz ? in1 : in0;
    __nv_bfloat16* oH = zz ? o1H : o0H;
    __nv_bfloat16* oL = zz ? o1L : o0L;
    __shared__ float tile[64][33];
    const int n0 = blockIdx.x * 32, k0 = blockIdx.y * 64;
    const int tid = threadIdx.x;
    // load 64x32 floats, coalesced on n
#pragma unroll
    for (int i = 0; i < 8; i++) {
        int idx = tid + i * 256;
        int r = idx >> 5, c = idx & 31;
        tile[r][c] = in[(size_t)(k0 + r) * N + n0 + c];
    }
    __syncthreads();
    // write 32 n-rows x 32 k-pairs as bf16x2, coalesced on k-pairs
    __nv_bfloat162* oH2 = (__nv_bfloat162*)oH;
    __nv_bfloat162* oL2 = (__nv_bfloat162*)oL;
#pragma unroll
    for (int i = 0; i < 4; i++) {
        int idx = tid + i * 256;
        int nr = idx >> 5, pc = idx & 31;
        float v0 = tile[2 * pc + 0][nr];
        float v1 = tile[2 * pc + 1][nr];
        float l0, l1;
        size_t o = ((size_t)(n0 + nr) * K + k0) / 2 + pc;
        oH2[o] = pack2h(v0, v1, l0, l1);
        oL2[o] = pack2(l0, l1);
    }
}

// ------------------------- streaming combine: out = g*h + (1-g)*r -----------
__global__ __launch_bounds__(256) void combine_kernel(
    const float* __restrict__ g, const float* __restrict__ h,
    const float* __restrict__ r, float* __restrict__ out, int n4)
{
    int i = blockIdx.x * 256 + threadIdx.x;
    if (i < n4) {
        float4 gv = ((const float4*)g)[i];
        float4 hv = ((const float4*)h)[i];
        float4 rv = ((const float4*)r)[i];
        float4 o;
        o.x = gv.x * hv.x + (1.f - gv.x) * rv.x;
        o.y = gv.y * hv.y + (1.f - gv.y) * rv.y;
        o.z = gv.z * hv.z + (1.f - gv.z) * rv.z;
        o.w = gv.w * hv.w + (1.f - gv.w) * rv.w;
        ((float4*)out)[i] = o;
    }
}

// ------------------------- core mainloop (shared, = R14) ---------------------
__device__ __forceinline__ void load_stage4(
    uint32_t sbase,
    const __nv_bfloat16* __restrict__ Ah, const __nv_bfloat16* __restrict__ Al,
    const __nv_bfloat16* __restrict__ Bh, const __nv_bfloat16* __restrict__ Bl,
    int aRow0, int bRow0, int K, int k0, int tid)
{
#pragma unroll
    for (int i = 0; i < 4; i++) {
        int idx = tid + i * NTHR;
        int r = idx >> 2, c = idx & 3;
        uint32_t so = swz(r, c);
        size_t ga = (size_t)(aRow0 + r) * K + k0 + c * 8;
        size_t gb = (size_t)(bRow0 + r) * K + k0 + c * 8;
        cp16(sbase + OFF_AH + so, Ah + ga);
        cp16(sbase + OFF_AL + so, Al + ga);
        cp16(sbase + OFF_BH + so, Bh + gb);
        cp16(sbase + OFF_BL + so, Bl + gb);
    }
}

__device__ __forceinline__ void gemm_mainloop(
    uint32_t sm, float acc[4][8][4],
    const __nv_bfloat16* __restrict__ Ah, const __nv_bfloat16* __restrict__ Al,
    const __nv_bfloat16* __restrict__ Bh, const __nv_bfloat16* __restrict__ Bl,
    int blockM, int blockN, int K, int tid, int lane, int wm, int wn)
{
    const int nk = K / BK;
#pragma unroll
    for (int s = 0; s < STAGES - 1; s++) {
        load_stage4(sm + s * STAGE_BYTES, Ah, Al, Bh, Bl, blockM, blockN, K, s * BK, tid);
        CP_COMMIT();
    }
    const int aRow = lane & 15;
    const int aHi  = lane >> 4;
    const int bRow = wn + (lane & 7) + ((lane >> 4) << 3);
    const int bHi  = (lane >> 3) & 1;
    const int sA = ((aRow >> 1) & 3);
    const int sB = ((bRow >> 1) & 3);

    for (int t = 0; t < nk; t++) {
        CP_WAIT1();
        __syncthreads();
        const int pf = t + STAGES - 1;
        const uint32_t sb = sm + (t % STAGES) * STAGE_BYTES;

#pragma unroll
        for (int ks = 0; ks < 2; ks++) {
            const uint32_t aChunk = (uint32_t)(((ks * 2 + aHi) ^ sA) << 4);
            const uint32_t bChunk = (uint32_t)(((ks * 2 + bHi) ^ sB) << 4);
            uint32_t ah[4][4], al[4][4];
#pragma unroll
            for (int mt = 0; mt < 4; mt++) {
                const uint32_t ra = (uint32_t)((wm + mt * 16 + aRow) * 64) + aChunk;
                ldmx4(ah[mt], sb + OFF_AH + ra);
                ldmx4(al[mt], sb + OFF_AL + ra);
            }
            if (ks == 0) {
                if (pf < nk)
                    load_stage4(sm + (pf % STAGES) * STAGE_BYTES, Ah, Al, Bh, Bl,
                                blockM, blockN, K, pf * BK, tid);
                CP_COMMIT();
            }
            uint32_t bh[2][4], bl[2][4];
            {
                const uint32_t rg = (uint32_t)(bRow * 64) + bChunk;
                ldmx4(bh[0], sb + OFF_BH + rg);
                ldmx4(bl[0], sb + OFF_BL + rg);
            }
#pragma unroll
            for (int g = 0; g < 4; g++) {
                const int cur = g & 1;
                const int nxt = cur ^ 1;
                if (g < 3) {
                    const uint32_t rg = (uint32_t)((bRow + (g + 1) * 16) * 64) + bChunk;
                    ldmx4(bh[nxt], sb + OFF_BH + rg);
                    ldmx4(bl[nxt], sb + OFF_BL + rg);
                }
#pragma unroll
                for (int mt = 0; mt < 4; mt++) mma_bf16(acc[mt][2 * g + 0], ah[mt], bh[cur] + 0);
#pragma unroll
                for (int mt = 0; mt < 4; mt++) mma_bf16(acc[mt][2 * g + 1], ah[mt], bh[cur] + 2);
#pragma unroll
                for (int mt = 0; mt < 4; mt++) mma_bf16(acc[mt][2 * g + 0], ah[mt], bl[cur] + 0);
#pragma unroll
                for (int mt = 0; mt < 4; mt++) mma_bf16(acc[mt][2 * g + 1], ah[mt], bl[cur] + 2);
#pragma unroll
                for (int mt = 0; mt < 4; mt++) mma_bf16(acc[mt][2 * g + 0], al[mt], bh[cur] + 0);
#pragma unroll
                for (int mt = 0; mt < 4; mt++) mma_bf16(acc[mt][2 * g + 1], al[mt], bh[cur] + 2);
            }
        }
    }
    CP_WAIT0();
}

// ------------------------- GEMM kernels (= R14) ------------------------------
template <int OP>
__device__ __forceinline__ float epi_op(float acc, float b, float h, float r) {
    if (OP == OP_GELU) return gelu_exact(acc + b);
    if (OP == OP_GATE) { float g = sigmoidf_(acc + b); return g * h + (1.f - g) * r; }
    return acc;
}

template <int OP, bool WF32, bool WSPLIT>
__global__ __launch_bounds__(NTHR, 2) void mma_gemm_kernel(
    const __nv_bfloat16* __restrict__ Ah, const __nv_bfloat16* __restrict__ Al,
    const __nv_bfloat16* __restrict__ Bh, const __nv_bfloat16* __restrict__ Bl,
    const float* __restrict__ bias, const float* __restrict__ Hm,
    const float* __restrict__ Rm,
    float* __restrict__ CF, __nv_bfloat16* __restrict__ CH,
    __nv_bfloat16* __restrict__ CL, int M, int N, int K)
{
    extern __shared__ char smem[];
    const uint32_t sm = smem_u32(smem);
    const int tid  = threadIdx.x;
    const int lane = tid & 31;
    const int wid  = tid >> 5;
    const int blockM = blockIdx.x * BM;
    const int blockN = blockIdx.y * BN;
    const int wm = (wid >> 1) * 64;
    const int wn = (wid & 1) * 64;

    float acc[4][8][4];
#pragma unroll
    for (int i = 0; i < 4; i++)
#pragma unroll
        for (int j = 0; j < 8; j++)
#pragma unroll
            for (int e = 0; e < 4; e++) acc[i][j][e] = 0.f;

    gemm_mainloop(sm, acc, Ah, Al, Bh, Bl, blockM, blockN, K, tid, lane, wm, wn);

    const int r0 = lane >> 2;
    const int c0 = (lane & 3) * 2;
#pragma unroll
    for (int mt = 0; mt < 4; mt++) {
#pragma unroll
        for (int half = 0; half < 2; half++) {
            const int m = blockM + wm + mt * 16 + r0 + half * 8;
            const size_t base = (size_t)m * N;
#pragma unroll
            for (int nt = 0; nt < 8; nt++) {
                const int n = blockN + wn + nt * 8 + c0;
                float v0 = acc[mt][nt][half * 2 + 0];
                float v1 = acc[mt][nt][half * 2 + 1];
                float b0 = 0.f, b1 = 0.f, h0 = 0.f, h1 = 0.f, rr0 = 0.f, rr1 = 0.f;
                if (OP != OP_NONE) { b0 = bias[n]; b1 = bias[n + 1]; }
                if (OP == OP_GATE) {
                    float2 hh = *(const float2*)(Hm + base + n);
                    float2 rr = *(const float2*)(Rm + base + n);
                    h0 = hh.x; h1 = hh.y; rr0 = rr.x; rr1 = rr.y;
                }
                v0 = epi_op<OP>(v0, b0, h0, rr0);
                v1 = epi_op<OP>(v1, b1, h1, rr1);
                if (WF32) *(float2*)(CF + base + n) = make_float2(v0, v1);
                if (WSPLIT) {
                    float l0, l1;
                    __nv_bfloat162 ph = pack2h(v0, v1, l0, l1);
                    __nv_bfloat162 pl = pack2(l0, l1);
                    *(__nv_bfloat162*)(CH + base + n) = ph;
                    *(__nv_bfloat162*)(CL + base + n) = pl;
                }
            }
        }
    }
}

// merged post GEMM: z=0 dense->h2=gelu(acc+db), z=1 gate->g=sigmoid(acc+gb)
__global__ __launch_bounds__(NTHR, 2) void post_merged_kernel(
    const __nv_bfloat16* __restrict__ AdH, const __nv_bfloat16* __restrict__ AdL,
    const __nv_bfloat16* __restrict__ BdH, const __nv_bfloat16* __restrict__ BdL,
    const __nv_bfloat16* __restrict__ AgH, const __nv_bfloat16* __restrict__ AgL,
    const __nv_bfloat16* __restrict__ BgH, const __nv_bfloat16* __restrict__ BgL,
    const float* __restrict__ db, const float* __restrict__ gbv,
    float* __restrict__ h2, float* __restrict__ gbuf, int M, int N, int K)
{
    extern __shared__ char smem[];
    const uint32_t sm = smem_u32(smem);
    const int tid  = threadIdx.x;
    const int lane = tid & 31;
    const int wid  = tid >> 5;
    const int blockM = blockIdx.x * BM;
    const int blockN = blockIdx.y * BN;
    const int z = blockIdx.z;
    const int wm = (wid >> 1) * 64;
    const int wn = (wid & 1) * 64;

    const __nv_bfloat16* Ah = z ? AgH : AdH;
    const __nv_bfloat16* Al = z ? AgL : AdL;
    const __nv_bfloat16* Bh = z ? BgH : BdH;
    const __nv_bfloat16* Bl = z ? BgL : BdL;
    const float* bias = z ? gbv : db;
    float* CF = z ? gbuf : h2;

    float acc[4][8][4];
#pragma unroll
    for (int i = 0; i < 4; i++)
#pragma unroll
        for (int j = 0; j < 8; j++)
#pragma unroll
            for (int e = 0; e < 4; e++) acc[i][j][e] = 0.f;

    gemm_mainloop(sm, acc, Ah, Al, Bh, Bl, blockM, blockN, K, tid, lane, wm, wn);

    const int r0 = lane >> 2;
    const int c0 = (lane & 3) * 2;
#pragma unroll
    for (int mt = 0; mt < 4; mt++) {
#pragma unroll
        for (int half = 0; half < 2; half++) {
            const int m = blockM + wm + mt * 16 + r0 + half * 8;
            const size_t base = (size_t)m * N;
#pragma unroll
            for (int nt = 0; nt < 8; nt++) {
                const int n = blockN + wn + nt * 8 + c0;
                float v0 = acc[mt][nt][half * 2 + 0] + bias[n];
                float v1 = acc[mt][nt][half * 2 + 1] + bias[n + 1];
                if (z == 0) { v0 = gelu_exact(v0); v1 = gelu_exact(v1); }
                else        { v0 = sigmoidf_(v0);  v1 = sigmoidf_(v1);  }
                *(float2*)(CF + base + n) = make_float2(v0, v1);
            }
        }
    }
}

// ------------------------- launch ------------------------------------------
extern "C" void kernel_launch(void* const* d_in, const int* in_sizes, int n_in,
                              void* d_out, int out_size)
{
    const float* x      = (const float*)d_in[0];
    const float* preG   = (const float*)d_in[1];
    const float* preB   = (const float*)d_in[2];
    const float* preDw  = (const float*)d_in[3];
    const float* preDb  = (const float*)d_in[4];
    const float* preGw  = (const float*)d_in[5];
    const float* preGb  = (const float*)d_in[6];
    const float* core0  = (const float*)d_in[7];
    const float* core1  = (const float*)d_in[8];
    const float* core2  = (const float*)d_in[9];
    const float* postG  = (const float*)d_in[10];
    const float* postB  = (const float*)d_in[11];
    const float* postDw = (const float*)d_in[12];
    const float* postDb = (const float*)d_in[13];
    const float* postGw = (const float*)d_in[14];
    const float* postGb = (const float*)d_in[15];
    float* out = (float*)d_out;

    float *h1, *t, *h2, *gbuf, *a01;
    cudaGetSymbolAddress((void**)&h1,   g_h1);
    cudaGetSymbolAddress((void**)&t,    g_t);
    cudaGetSymbolAddress((void**)&h2,   g_h2);
    cudaGetSymbolAddress((void**)&gbuf, g_gb);
    cudaGetSymbolAddress((void**)&a01,  g_a01);

    __nv_bfloat16 *xH, *xL, *ln1H, *ln1L, *hpreH, *hpreL, *tH, *tL, *ln2H, *ln2L;
    __nv_bfloat16 *preDwTH, *preDwTL, *preGwTH, *preGwTL;
    __nv_bfloat16 *wttTH, *wttTL, *postDwTH, *postDwTL, *postGwTH, *postGwTL;
    cudaGetSymbolAddress((void**)&xH,    g_xH);    cudaGetSymbolAddress((void**)&xL,    g_xL);
    cudaGetSymbolAddress((void**)&ln1H,  g_ln1H);  cudaGetSymbolAddress((void**)&ln1L,  g_ln1L);
    cudaGetSymbolAddress((void**)&hpreH, g_hpreH); cudaGetSymbolAddress((void**)&hpreL, g_hpreL);
    cudaGetSymbolAddress((void**)&tH,    g_tH);    cudaGetSymbolAddress((void**)&tL,    g_tL);
    cudaGetSymbolAddress((void**)&ln2H,  g_ln2H);  cudaGetSymbolAddress((void**)&ln2L,  g_ln2L);
    cudaGetSymbolAddress((void**)&preDwTH,  g_preDwTH);  cudaGetSymbolAddress((void**)&preDwTL,  g_preDwTL);
    cudaGetSymbolAddress((void**)&preGwTH,  g_preGwTH);  cudaGetSymbolAddress((void**)&preGwTL,  g_preGwTL);
    cudaGetSymbolAddress((void**)&wttTH,    g_wttTH);    cudaGetSymbolAddress((void**)&wttTL,    g_wttTL);
    cudaGetSymbolAddress((void**)&postDwTH, g_postDwTH); cudaGetSymbolAddress((void**)&postDwTL, g_postDwTL);
    cudaGetSymbolAddress((void**)&postGwTH, g_postGwTH); cudaGetSymbolAddress((void**)&postGwTL, g_postGwTL);

    cudaFuncSetAttribute(mma_gemm_kernel<OP_GELU, true, false>,
                         cudaFuncAttributeMaxDynamicSharedMemorySize, GEMM_SMEM);
    cudaFuncSetAttribute(mma_gemm_kernel<OP_GATE, false, true>,
                         cudaFuncAttributeMaxDynamicSharedMemorySize, GEMM_SMEM);
    cudaFuncSetAttribute(mma_gemm_kernel<OP_NONE, true, true>,
                         cudaFuncAttributeMaxDynamicSharedMemorySize, GEMM_SMEM);
    cudaFuncSetAttribute(post_merged_kernel,
                         cudaFuncAttributeMaxDynamicSharedMemorySize, GEMM_SMEM);

    // --- operator prep (independent of x) ---
    build_a01_kernel<<<131072 / 256, 256>>>(core0, core1, a01);
    build_wttT_kernel<<<(DIN * DOUT / 2) / 256, 256>>>(a01, core2, wttTH, wttTL);
    transpose_split2_kernel<<<dim3(DIN / 32, DIN / 64, 2), 256>>>(
        preDw, preDwTH, preDwTL, preGw, preGwTH, preGwTL, DIN, DIN);
    transpose_split2_kernel<<<dim3(DOUT / 32, DOUT / 64, 2), 256>>>(
        postDw, postDwTH, postDwTL, postGw, postGwTH, postGwTL, DOUT, DOUT);

    // --- pre block ---
    layernorm_split_kernel<DIN / 512, true><<<NTOK, 256>>>(
        x, preG, preB, ln1H, ln1L, xH, xL, DIN);
    mma_gemm_kernel<OP_GELU, true, false><<<dim3(NTOK / BM, DIN / BN), NTHR, GEMM_SMEM>>>(
        ln1H, ln1L, preDwTH, preDwTL, preDb, nullptr, nullptr,
        h1, nullptr, nullptr, NTOK, DIN, DIN);
    mma_gemm_kernel<OP_GATE, false, true><<<dim3(NTOK / BM, DIN / BN), NTHR, GEMM_SMEM>>>(
        xH, xL, preGwTH, preGwTL, preGb, h1, x,
        nullptr, hpreH, hpreL, NTOK, DIN, DIN);

    // --- TT contraction ---
    mma_gemm_kernel<OP_NONE, true, true><<<dim3(NTOK / BM, DOUT / BN), NTHR, GEMM_SMEM>>>(
        hpreH, hpreL, wttTH, wttTL, nullptr, nullptr, nullptr,
        t, tH, tL, NTOK, DOUT, DIN);

    // --- post block: LN, merged dense+gate (z), streaming combine ---
    layernorm_split_kernel<DOUT / 512, false><<<NTOK, 256>>>(
        t, postG, postB, ln2H, ln2L, nullptr, nullptr, DOUT);
    post_merged_kernel<<<dim3(NTOK / BM, DOUT / BN, 2), NTHR, GEMM_SMEM>>>(
        ln2H, ln2L, postDwTH, postDwTL,
        tH, tL, postGwTH, postGwTL,
        postDb, postGb, h2, gbuf, NTOK, DOUT, DOUT);
    combine_kernel<<<(NTOK * DOUT / 4 + 255) / 256, 256>>>(
        gbuf, h2, t, out, NTOK * DOUT / 4);
}